// round 17
// baseline (speedup 1.0000x reference)
#include <cuda_runtime.h>
#include <cuda_fp16.h>

// x: (16, 2, 1024, 1024) fp32, 20 diffusion steps. Weights exact in fp32:
// hx = hy = 0.25, center = 0 -> one step == 0.25*(L+R+U+D).
// K=7+7+6 passes, FADD-only unscaled stages, deferred exact 0.25^K scale,
// fp16 inter-pass buffers (validated err model: ~8e-5).
// Round 17: (1) ld.cs on pass-1 fp32 reads so the single-use x stream stops
// evicting the 67 MB fp16 write-set -> passes 2-3 read from L2;
// (2) st.cs only on the final fp32 output (dead after store);
// (3) stage sum reassociated (lv+B)+(A+D): fresh-D chain 3->2 FADD/stage.
#define HH 1024
#define WW 1024
#define NPLANES 32
#define PLANE_ELEMS (HH * WW)
#define RB 128         // output rows per warp-band
#define NSTRIP 9       // strip j input base = 112*j, window 128 cols

__device__ float g_scratch[NPLANES * PLANE_ELEMS];   // holds two 67 MB fp16 buffers

__device__ __forceinline__ int reflect_row(int i) {
    i = (i < 0) ? -i : i;
    return (i >= HH) ? (2 * HH - 2 - i) : i;
}

// ---- typed row load/store: 4 consecutive elements at (row, cols 4g..4g+3) ----
template<bool CS>
__device__ __forceinline__ float4 ld4(const float* p, int row, int g) {
    const float* a = p + (size_t)row * WW + 4 * (size_t)g;
    float4 v;
    if (CS) {
        asm volatile("ld.global.cs.v4.f32 {%0, %1, %2, %3}, [%4];"
                     : "=f"(v.x), "=f"(v.y), "=f"(v.z), "=f"(v.w) : "l"(a));
    } else {
        v = *(const float4*)a;
    }
    return v;
}
template<bool CS>
__device__ __forceinline__ float4 ld4(const __half* p, int row, int g) {
    const uint2 raw = *(const uint2*)(p + (size_t)row * WW + 4 * (size_t)g);
    const __half2 h0 = *reinterpret_cast<const __half2*>(&raw.x);
    const __half2 h1 = *reinterpret_cast<const __half2*>(&raw.y);
    const float2 f0 = __half22float2(h0);
    const float2 f1 = __half22float2(h1);
    return make_float4(f0.x, f0.y, f1.x, f1.y);
}
template<bool CS>
__device__ __forceinline__ void st4(float* p, int row, int g, float4 v) {
    float* a = p + (size_t)row * WW + 4 * (size_t)g;
    if (CS) {
        asm volatile("st.global.cs.v4.f32 [%0], {%1, %2, %3, %4};"
                     :: "l"(a), "f"(v.x), "f"(v.y), "f"(v.z), "f"(v.w) : "memory");
    } else {
        *(float4*)a = v;
    }
}
template<bool CS>
__device__ __forceinline__ void st4(__half* p, int row, int g, float4 v) {
    const __half2 h0 = __floats2half2_rn(v.x, v.y);
    const __half2 h1 = __floats2half2_rn(v.z, v.w);
    uint2 raw;
    raw.x = *reinterpret_cast<const unsigned*>(&h0);
    raw.y = *reinterpret_cast<const unsigned*>(&h1);
    *(uint2*)(p + (size_t)row * WW + 4 * (size_t)g) = raw;   // plain: next pass reads it
}

template<int KK, bool EDGEL, bool EDGER, bool LDCS, bool STCS, typename TIN, typename TOUT>
__device__ __forceinline__ void run_band(
    const TIN* __restrict__ sp, TOUT* __restrict__ dp,
    int g, int r0, int lane, float final_scale)
{
    // Interior strips keep lanes 2..29 (8-col halo/side covers KK<=8 stages
    // of 1-col/side garbage). Edge strips extend to the mirrored boundary.
    const int lo = EDGEL ? 0 : 2;
    const int hi = EDGER ? 31 : 29;
    const bool do_store = (lane >= lo && lane <= hi);
    const bool fixL = EDGEL && (lane == 0);
    const bool fixR = EDGER && (lane == 31);

    // Rolling window per stage s: a[s] = v_s[row-2], b[s] = v_s[row-1]
    // (v_s are UNSCALED partial sums: v_s = 4^s * u_s).
    float4 a[KK], b[KK];
#pragma unroll
    for (int s = 0; s < KK; ++s) {
        a[s] = make_float4(0.f, 0.f, 0.f, 0.f);
        b[s] = make_float4(0.f, 0.f, 0.f, 0.f);
    }

    const int niter = RB + 2 * KK;   // 142 (K=7) / 140 (K=6) — even

    // Prefetch pipeline, depth 2 (reflect keeps all rows in-bounds).
    float4 p0 = ld4<LDCS>(sp, reflect_row(r0 - KK),     g);
    float4 p1 = ld4<LDCS>(sp, reflect_row(r0 - KK + 1), g);

#pragma unroll 2
    for (int m = 0; m < niter; ++m) {
        const int i = r0 - KK + m;   // input row index for stage 0

        // Shuffle batch: operands are iteration-start state only.
        float lv[KK], rv[KK];
#pragma unroll
        for (int s = 0; s < KK; ++s) {
            const float lu = __shfl_up_sync(0xffffffffu, b[s].w, 1);
            const float rd = __shfl_down_sync(0xffffffffu, b[s].x, 1);
            lv[s] = fixL ? b[s].y : lu;   // mirror col -1 -> col 1
            rv[s] = fixR ? b[s].z : rd;   // mirror col 1024 -> col 1022
        }

        float4 cur[KK + 1];
        cur[0] = p0;
        p0 = p1;
        p1 = ld4<LDCS>(sp, reflect_row(i + 2), g);

#pragma unroll
        for (int s = 1; s <= KK; ++s) {
            const float4 B = b[s - 1];    // center row (iter-start state)
            const float4 A = a[s - 1];    // up row     (iter-start state)
            const float4 D = cur[s - 1];  // down row   (fresh)

            // Reassociated: o = (L+R) + (A+D). Fresh-D chain = 2 FADD/stage.
            float4 h;
            h.x = lv[s - 1] + B.y;
            h.y = B.x + B.z;
            h.z = B.y + B.w;
            h.w = B.z + rv[s - 1];

            float4 t;
            t.x = A.x + D.x;
            t.y = A.y + D.y;
            t.z = A.z + D.z;
            t.w = A.w + D.w;

            float4 o;
            o.x = h.x + t.x;
            o.y = h.y + t.y;
            o.z = h.z + t.z;
            o.w = h.w + t.w;
            cur[s] = o;
        }

        // Final-stage row j = i - KK is a band row exactly when m >= 2*KK.
        if (m >= 2 * KK && do_store) {
            float4 o;
            o.x = cur[KK].x * final_scale;
            o.y = cur[KK].y * final_scale;
            o.z = cur[KK].z * final_scale;
            o.w = cur[KK].w * final_scale;
            st4<STCS>(dp, i - KK, g, o);
        }

#pragma unroll
        for (int s = 0; s < KK; ++s) {
            a[s] = b[s];
            b[s] = cur[s];
        }
    }
}

template<int KK, bool LDCS, bool STCS, typename TIN, typename TOUT>
__global__ __launch_bounds__(256, 2)
void fused_stencil(const TIN* __restrict__ src,
                   TOUT* __restrict__ dst,
                   float final_scale)
{
    const int strip = blockIdx.x;          // 0..8
    const int img   = blockIdx.y;          // 0..31
    const int warp  = threadIdx.x >> 5;    // band 0..7
    const int lane  = threadIdx.x & 31;

    const TIN* sp = src + (size_t)img * PLANE_ELEMS;
    TOUT*      dp = dst + (size_t)img * PLANE_ELEMS;

    const int g  = ((strip * 112) >> 2) + lane;   // lane's 4-col group index
    const int r0 = warp * RB;

    if (strip == 0) {
        run_band<KK, true, false, LDCS, STCS>(sp, dp, g, r0, lane, final_scale);
    } else if (strip == NSTRIP - 1) {
        run_band<KK, false, true, LDCS, STCS>(sp, dp, g, r0, lane, final_scale);
    } else {
        run_band<KK, false, false, LDCS, STCS>(sp, dp, g, r0, lane, final_scale);
    }
}

extern "C" void kernel_launch(void* const* d_in, const int* in_sizes, int n_in,
                              void* d_out, int out_size)
{
    const float* x = (const float*)d_in[0];
    float* out = (float*)d_out;

    float* scratch = nullptr;
    cudaGetSymbolAddress((void**)&scratch, g_scratch);

    // Two fp16 buffers carved from the 128 MB fp32 scratch (67 MB each).
    __half* h0 = (__half*)scratch;
    __half* h1 = h0 + (size_t)NPLANES * PLANE_ELEMS;

    dim3 grid(NSTRIP, NPLANES);   // 9 strips x 32 planes = 288 blocks
    dim3 block(256);              // 8 warps = 8 row bands of 128 rows

    // 7 + 7 + 6 = 20 steps. Pass 1: evict-first x reads (protect h0 in L2),
    // plain h0 stores. Pass 2: plain (h0 reads hit L2, h1 stays resident).
    // Pass 3: plain h1 reads (L2 hit), evict-first final fp32 stores.
    fused_stencil<7, true,  false><<<grid, block>>>(x,  h0,  1.0f / 16384.0f);
    fused_stencil<7, false, false><<<grid, block>>>(h0, h1,  1.0f / 16384.0f);
    fused_stencil<6, false, true ><<<grid, block>>>(h1, out, 1.0f / 4096.0f);
}